// round 2
// baseline (speedup 1.0000x reference)
#include <cuda_runtime.h>
#include <math.h>

// AdderNet: 4 layers of adder-conv (-sum|patch - w|) + affine/relu + log_softmax.
// B=4096. Layouts are [b][c][y][x] contiguous per image.
//
// Scratch (device globals, no allocation):
#define B 4096

__device__ float g_a1[B * 16 * 13 * 13];   // 44.3 MB
__device__ float g_a2[B * 32 * 7 * 7];     // 25.7 MB
__device__ float g_a3[B * 16 * 4 * 4];     //  4.2 MB

// ---------------------------------------------------------------------------
// Layer 1: x[B,1,28,28] (-0.5) -> a1[B,16,13,13], stride 2, pad 0
// out = relu((10 - sum)/4)
// Flat pixel-per-thread; each thread does all 16 channels with its 9-elem
// patch in registers. Weights (144 f) in smem.
// ---------------------------------------------------------------------------
__global__ __launch_bounds__(256) void k_layer1(const float* __restrict__ x,
                                                const float* __restrict__ w1,
                                                float* __restrict__ a1) {
    __shared__ float ws[16 * 9];
    int t = threadIdx.x;
    if (t < 144) ws[t] = w1[t];
    __syncthreads();

    int idx = blockIdx.x * 256 + t;            // global pixel id, exact grid
    int b = idx / 169;
    int pix = idx % 169;
    int py = pix / 13, px = pix % 13;
    const float* xb = x + b * 784;

    float patch[9];
#pragma unroll
    for (int kh = 0; kh < 3; kh++)
#pragma unroll
        for (int kw = 0; kw < 3; kw++)
            patch[kh * 3 + kw] = xb[(py * 2 + kh) * 28 + (px * 2 + kw)] - 0.5f;

    float* out = a1 + b * 2704 + pix;
#pragma unroll
    for (int o = 0; o < 16; o++) {
        float s = 0.f;
#pragma unroll
        for (int p = 0; p < 9; p++) s += fabsf(patch[p] - ws[o * 9 + p]);
        out[o * 169] = fmaxf((10.0f - s) * 0.25f, 0.0f);
    }
}

// ---------------------------------------------------------------------------
// Layer 2 (dominant, 70% of flops): a1[B,16,13,13] -> a2[B,32,7,7],
// stride 2, pad 1. out = relu((130 - sum)/8).
// One CTA per image, 196 threads = 49 pixels x 4 channel-groups.
// Zero-padded input tile 16x15x15 + full w2 in smem. 8 accumulators/thread:
// per patch element: 1 LDS (input, warp-broadcastable-ish) + 8 LDS (weights,
// uniform within warp -> broadcast) + 16 FADD  => fma-pipe bound.
// ---------------------------------------------------------------------------
__global__ __launch_bounds__(196) void k_layer2(const float* __restrict__ a1,
                                                const float* __restrict__ w2,
                                                float* __restrict__ a2) {
    __shared__ float sp[16 * 15 * 15];   // 3600 f, zero-padded input
    __shared__ float ws[32 * 144];       // 4608 f

    int t = threadIdx.x;
    int b = blockIdx.x;

    for (int i = t; i < 3600; i += 196) sp[i] = 0.f;
    __syncthreads();
    const float* src = a1 + b * 2704;
    for (int i = t; i < 2704; i += 196) {
        int c = i / 169, r = i % 169, y = r / 13, xx = r % 13;
        sp[c * 225 + (y + 1) * 15 + (xx + 1)] = src[i];
    }
    for (int i = t; i < 4608; i += 196) ws[i] = w2[i];
    __syncthreads();

    int pix = t % 49;
    int og = t / 49;                    // 0..3, exact
    int py = pix / 7, px = pix % 7;
    const float* base = sp + py * 2 * 15 + px * 2;
    const float* wb = ws + og * 8 * 144;

    float acc[8];
#pragma unroll
    for (int j = 0; j < 8; j++) acc[j] = 0.f;

    for (int c = 0; c < 16; c++) {
        const float* pc = base + c * 225;
        const float* wc = wb + c * 9;
#pragma unroll
        for (int k = 0; k < 9; k++) {
            float v = pc[(k / 3) * 15 + (k % 3)];
#pragma unroll
            for (int j = 0; j < 8; j++) acc[j] += fabsf(v - wc[j * 144 + k]);
        }
    }

    float* out = a2 + b * 1568 + og * 8 * 49 + pix;
#pragma unroll
    for (int j = 0; j < 8; j++)
        out[j * 49] = fmaxf((130.0f - acc[j]) * 0.125f, 0.0f);
}

// ---------------------------------------------------------------------------
// Layer 3: a2[B,32,7,7] -> a3[B,16,4,4], stride 2, pad 1.
// out = relu((280 - sum)/16). One CTA per image, 128 threads =
// 16 pixels x 8 groups (2 channels each).
// ---------------------------------------------------------------------------
__global__ __launch_bounds__(128) void k_layer3(const float* __restrict__ a2,
                                                const float* __restrict__ w3,
                                                float* __restrict__ a3) {
    __shared__ float sp[32 * 9 * 9];     // 2592 f, zero-padded
    __shared__ float ws[16 * 288];       // 4608 f

    int t = threadIdx.x;
    int b = blockIdx.x;

    for (int i = t; i < 2592; i += 128) sp[i] = 0.f;
    __syncthreads();
    const float* src = a2 + b * 1568;
    for (int i = t; i < 1568; i += 128) {
        int c = i / 49, r = i % 49, y = r / 7, xx = r % 7;
        sp[c * 81 + (y + 1) * 9 + (xx + 1)] = src[i];
    }
    for (int i = t; i < 4608; i += 128) ws[i] = w3[i];
    __syncthreads();

    int pix = t % 16;
    int og = t / 16;                    // 0..7
    int py = pix / 4, px = pix % 4;
    const float* base = sp + py * 2 * 9 + px * 2;
    const float* wb = ws + og * 2 * 288;

    float acc0 = 0.f, acc1 = 0.f;
    for (int c = 0; c < 32; c++) {
        const float* pc = base + c * 81;
        const float* wc = wb + c * 9;
#pragma unroll
        for (int k = 0; k < 9; k++) {
            float v = pc[(k / 3) * 9 + (k % 3)];
            acc0 += fabsf(v - wc[k]);
            acc1 += fabsf(v - wc[288 + k]);
        }
    }

    float* out = a3 + b * 256 + og * 2 * 16 + pix;
    out[0]  = fmaxf((280.0f - acc0) * 0.0625f, 0.0f);
    out[16] = fmaxf((280.0f - acc1) * 0.0625f, 0.0f);
}

// ---------------------------------------------------------------------------
// Layer 4 + log_softmax: a3[B,16,4,4] -> out[B,10].
// Patch = input[:, 0:3, 0:3] (k=3, s=2, p=0 on 4x4 -> 1x1).
// One warp per image (4 images / 128-thread CTA); lanes 0..9 each do one
// output channel; warp-shuffle max / sum-exp for log_softmax.
// ---------------------------------------------------------------------------
__global__ __launch_bounds__(128) void k_layer4(const float* __restrict__ a3,
                                                const float* __restrict__ w4,
                                                float* __restrict__ out) {
    __shared__ float ws[10 * 144];   // 1440 f
    __shared__ float xs[4 * 256];

    int t = threadIdx.x;
    for (int i = t; i < 1440; i += 128) ws[i] = w4[i];

    int warp = t / 32, lane = t % 32;
    int b = blockIdx.x * 4 + warp;
    const float* src = a3 + b * 256;
    for (int i = lane; i < 256; i += 32) xs[warp * 256 + i] = src[i];
    __syncthreads();

    float logit = -1e30f;
    if (lane < 10) {
        const float* wp = ws + lane * 144;
        const float* xp = xs + warp * 256;
        float s = 0.f;
        for (int c = 0; c < 16; c++) {
#pragma unroll
            for (int k = 0; k < 9; k++)
                s += fabsf(xp[c * 16 + (k / 3) * 4 + (k % 3)] - wp[c * 9 + k]);
        }
        logit = -s;
    }

    // log_softmax over lanes 0..9 (inactive lanes: logit=-1e30, e=0)
    float m = logit;
#pragma unroll
    for (int off = 16; off; off >>= 1)
        m = fmaxf(m, __shfl_xor_sync(0xffffffffu, m, off));
    float e = (lane < 10) ? expf(logit - m) : 0.f;
    float sum = e;
#pragma unroll
    for (int off = 16; off; off >>= 1)
        sum += __shfl_xor_sync(0xffffffffu, sum, off);

    if (lane < 10) out[b * 10 + lane] = logit - m - logf(sum);
}

// ---------------------------------------------------------------------------
extern "C" void kernel_launch(void* const* d_in, const int* in_sizes, int n_in,
                              void* d_out, int out_size) {
    const float* x  = (const float*)d_in[0];
    const float* w1 = (const float*)d_in[1];
    const float* w2 = (const float*)d_in[2];
    const float* w3 = (const float*)d_in[3];
    const float* w4 = (const float*)d_in[4];
    float* out = (float*)d_out;

    float *a1, *a2, *a3;
    cudaGetSymbolAddress((void**)&a1, g_a1);
    cudaGetSymbolAddress((void**)&a2, g_a2);
    cudaGetSymbolAddress((void**)&a3, g_a3);

    k_layer1<<<(B * 169) / 256, 256>>>(x, w1, a1);     // 692224/256 = 2704 exact
    k_layer2<<<B, 196>>>(a1, w2, a2);
    k_layer3<<<B, 128>>>(a2, w3, a3);
    k_layer4<<<B / 4, 128>>>(a3, w4, out);
}